// round 6
// baseline (speedup 1.0000x reference)
#include <cuda_runtime.h>
#include <cuda_fp16.h>

// CapsuleLayer dynamic routing — fp16-materialized u_hat, W-reuse GEMM,
// barrier-free warp-per-b routing pass.
// u [32,2048,16] f32, W [2048,16,1024] f32, out [32,1024] f32.

#define BB    32
#define NN    2048
#define KK    16
#define OUTC  1024
#define NCHK  148          // one block (chunk) per SM
#define MAXCH 14           // ceil(2048/148)

typedef unsigned long long ull;

// ---- scratch (device globals; runtime allocation is forbidden) ----
__device__ __half g_uhat_h[(size_t)BB * NN * OUTC];   // 134 MB
__device__ float  g_opart[(size_t)NCHK * BB * OUTC];  // 19.4 MB
__device__ float  g_o[BB * OUTC];

__device__ __forceinline__ void ffma2(ull& d, ull a, ull b) {
    asm("fma.rn.f32x2 %0, %1, %2, %0;" : "+l"(d) : "l"(a), "l"(b));
}
__device__ __forceinline__ void fadd2(ull& d, ull a) {
    asm("add.rn.f32x2 %0, %0, %1;" : "+l"(d) : "l"(a));
}
__device__ __forceinline__ ull dup2(float x) {
    ull r; asm("mov.b64 %0, {%1, %1};" : "=l"(r) : "f"(x)); return r;
}
__device__ __forceinline__ ull f2u(float x, float y) {
    ull r; asm("mov.b64 %0, {%1, %2};" : "=l"(r) : "f"(x), "f"(y)); return r;
}
__device__ __forceinline__ float2 u2f(ull v) {
    float2 f; asm("mov.b64 {%0, %1}, %2;" : "=f"(f.x), "=f"(f.y) : "l"(v)); return f;
}

// ============ pass0: u_hat = u @ W (store fp16), + iteration-0 partials ======
// 1024 threads: cv = tid&255 (4 consecutive c), bg = tid>>8 (8 b's).
// u staged in smem once per block: W reuse x8 per load, one barrier total.
__global__ __launch_bounds__(1024, 1)
void caps_pass0(const float* __restrict__ u, const float* __restrict__ W)
{
    __shared__ float4 u_s[MAXCH][BB][KK / 4];

    const int cv  = threadIdx.x & 255;      // vector column (4 floats)
    const int b0  = (threadIdx.x >> 8) * 8; // batch group base
    const int n0  = (int)(((long long)blockIdx.x * NN) / NCHK);
    const int n1  = (int)(((long long)(blockIdx.x + 1) * NN) / NCHK);
    const int cnt = n1 - n0;

    // stage u[b][n0..n1][k] into smem (coalesced-ish, tiny: <=28KB)
    for (int idx = threadIdx.x; idx < cnt * BB * KK; idx += 1024) {
        int nn = idx >> 9, rem = idx & 511;
        int b = rem >> 4, k = rem & 15;
        reinterpret_cast<float*>(&u_s[nn][b][0])[k] =
            u[((size_t)b * NN + (n0 + nn)) * KK + k];
    }
    __syncthreads();

    ull acc01[8], acc23[8];
    #pragma unroll
    for (int b = 0; b < 8; b++) { acc01[b] = 0ull; acc23[b] = 0ull; }

    const ulonglong2* Wv = reinterpret_cast<const ulonglong2*>(W) + cv;

    for (int nn = 0; nn < cnt; nn++) {
        const int n = n0 + nn;
        const ulonglong2* Wn = Wv + (size_t)n * KK * (OUTC / 4);

        ull t01[8], t23[8];
        #pragma unroll
        for (int b = 0; b < 8; b++) { t01[b] = 0ull; t23[b] = 0ull; }

        #pragma unroll
        for (int k4 = 0; k4 < KK / 4; k4++) {
            ulonglong2 wa = Wn[(size_t)(k4 * 4 + 0) * (OUTC / 4)];
            ulonglong2 wb = Wn[(size_t)(k4 * 4 + 1) * (OUTC / 4)];
            ulonglong2 wc = Wn[(size_t)(k4 * 4 + 2) * (OUTC / 4)];
            ulonglong2 wd = Wn[(size_t)(k4 * 4 + 3) * (OUTC / 4)];
            #pragma unroll
            for (int b = 0; b < 8; b++) {
                float4 uv = u_s[nn][b0 + b][k4];   // LDS.128 broadcast
                ffma2(t01[b], dup2(uv.x), wa.x); ffma2(t23[b], dup2(uv.x), wa.y);
                ffma2(t01[b], dup2(uv.y), wb.x); ffma2(t23[b], dup2(uv.y), wb.y);
                ffma2(t01[b], dup2(uv.z), wc.x); ffma2(t23[b], dup2(uv.z), wc.y);
                ffma2(t01[b], dup2(uv.w), wd.x); ffma2(t23[b], dup2(uv.w), wd.y);
            }
        }

        #pragma unroll
        for (int b = 0; b < 8; b++) {
            fadd2(acc01[b], t01[b]);
            fadd2(acc23[b], t23[b]);
            float2 f01 = u2f(t01[b]), f23 = u2f(t23[b]);
            __half2 h01 = __float22half2_rn(make_float2(f01.x, f01.y));
            __half2 h23 = __float22half2_rn(make_float2(f23.x, f23.y));
            uint2 st;
            st.x = *reinterpret_cast<unsigned*>(&h01);
            st.y = *reinterpret_cast<unsigned*>(&h23);
            *reinterpret_cast<uint2*>(
                &g_uhat_h[((size_t)(b0 + b) * NN + n) * OUTC + cv * 4]) = st;
        }
    }

    #pragma unroll
    for (int b = 0; b < 8; b++) {
        float2 f01 = u2f(acc01[b]), f23 = u2f(acc23[b]);
        float4 sa = make_float4(f01.x, f01.y, f23.x, f23.y);
        *reinterpret_cast<float4*>(
            &g_opart[((size_t)blockIdx.x * BB + (b0 + b)) * OUTC + cv * 4]) = sa;
    }
}

// ====== pass1: warp-per-b routing: logits + softmax + o accumulation ========
// 1024 threads = 32 warps = 32 b's; lane = capsule i. No smem, no barriers.
__global__ __launch_bounds__(1024, 1)
void caps_pass1()
{
    const int lane = threadIdx.x & 31;   // capsule i
    const int b    = threadIdx.x >> 5;   // warp id == batch
    const int n0   = (int)(((long long)blockIdx.x * NN) / NCHK);
    const int n1   = (int)(((long long)(blockIdx.x + 1) * NN) / NCHK);
    const int cnt  = n1 - n0;

    // o[b, i, 0..31] -> 16 f32x2 registers
    ull o2[16];
    {
        const float4* op = reinterpret_cast<const float4*>(g_o + b * OUTC + lane * 32);
        #pragma unroll
        for (int q = 0; q < 8; q++) {
            float4 v = op[q];
            o2[q * 2 + 0] = f2u(v.x, v.y);
            o2[q * 2 + 1] = f2u(v.z, v.w);
        }
    }

    ull acc2[16];
    #pragma unroll
    for (int j = 0; j < 16; j++) acc2[j] = 0ull;

    // u_hat row for (b, n): 1024 halves; this lane's 32 halves = 4 uint4
    const uint4* base = reinterpret_cast<const uint4*>(g_uhat_h)
                      + ((size_t)b * NN + n0) * (OUTC / 8) + lane * 4;

    uint4 A0[4], A1[4];
    #pragma unroll
    for (int q = 0; q < 4; q++) A0[q] = base[q];
    if (cnt > 1) {
        #pragma unroll
        for (int q = 0; q < 4; q++) A1[q] = base[(OUTC / 8) + q];
    }

    for (int idx = 0; idx < cnt; idx++) {
        // convert current 32 halves -> 16 f32x2
        ull uh2[16];
        #pragma unroll
        for (int q = 0; q < 4; q++) {
            const unsigned* p = reinterpret_cast<const unsigned*>(&A0[q]);
            #pragma unroll
            for (int h = 0; h < 4; h++) {
                __half2 hv = *reinterpret_cast<const __half2*>(&p[h]);
                float2 fv = __half22float2(hv);
                uh2[q * 4 + h] = f2u(fv.x, fv.y);
            }
        }

        // shift prefetch pipeline
        #pragma unroll
        for (int q = 0; q < 4; q++) A0[q] = A1[q];
        if (idx + 2 < cnt) {
            #pragma unroll
            for (int q = 0; q < 4; q++)
                A1[q] = base[(size_t)(idx + 2) * (OUTC / 8) + q];
        }

        // logit: <o[b,i,:], u_hat[b,n,i*32:]> — thread-local dot
        ull l2 = 0ull;
        #pragma unroll
        for (int j = 0; j < 16; j++) ffma2(l2, uh2[j], o2[j]);
        float2 lf = u2f(l2);
        float p = lf.x + lf.y;

        // softmax over capsules (warp-wide)
        float m = p;
        #pragma unroll
        for (int off = 16; off > 0; off >>= 1)
            m = fmaxf(m, __shfl_xor_sync(0xffffffffu, m, off));
        float e = __expf(p - m);
        float s = e;
        #pragma unroll
        for (int off = 16; off > 0; off >>= 1)
            s += __shfl_xor_sync(0xffffffffu, s, off);
        ull c2 = dup2(e / s);

        #pragma unroll
        for (int j = 0; j < 16; j++) ffma2(acc2[j], c2, uh2[j]);
    }

    float* dst = g_opart + ((size_t)blockIdx.x * BB + b) * OUTC + lane * 32;
    #pragma unroll
    for (int q = 0; q < 8; q++) {
        float2 f0 = u2f(acc2[q * 2 + 0]), f1 = u2f(acc2[q * 2 + 1]);
        *reinterpret_cast<float4*>(dst + q * 4) =
            make_float4(f0.x, f0.y, f1.x, f1.y);
    }
}

// ============ reduce: sum chunks, l2-normalize (->g_o) or squash (->out) =====
__global__ __launch_bounds__(128)
void caps_reduce(float* __restrict__ out, int mode)
{
    const int b   = blockIdx.x;
    const int col = blockIdx.y * 128 + threadIdx.x;

    const float* p = g_opart + (size_t)b * OUTC + col;
    float s = 0.f;
    int ch = 0;
    #pragma unroll 1
    for (; ch + 4 <= NCHK; ch += 4) {
        float t0 = p[(size_t)(ch + 0) * BB * OUTC];
        float t1 = p[(size_t)(ch + 1) * BB * OUTC];
        float t2 = p[(size_t)(ch + 2) * BB * OUTC];
        float t3 = p[(size_t)(ch + 3) * BB * OUTC];
        s += (t0 + t1) + (t2 + t3);
    }
    for (; ch < NCHK; ch++) s += p[(size_t)ch * BB * OUTC];

    if (mode == 0) s *= (1.0f / 32.0f);

    float q = s * s;
    #pragma unroll
    for (int off = 16; off > 0; off >>= 1)
        q += __shfl_xor_sync(0xffffffffu, q, off);

    if (mode < 2) {
        g_o[b * OUTC + col] = s * rsqrtf(fmaxf(q, 1e-12f));            // l2_normalize
    } else {
        out[(size_t)b * OUTC + col] = (q / (1.f + q)) * s * rsqrtf(q + 1e-7f);  // squash
    }
}

extern "C" void kernel_launch(void* const* d_in, const int* in_sizes, int n_in,
                              void* d_out, int out_size)
{
    const float* u = (const float*)d_in[0];
    const float* W = (const float*)d_in[1];
    if (n_in >= 2 && in_sizes[0] > in_sizes[1]) {  // defensive: u is the smaller input
        const float* t = u; u = W; W = t;
    }
    float* out = (float*)d_out;

    dim3 rgrid(BB, 8);

    caps_pass0<<<NCHK, 1024>>>(u, W);
    caps_reduce<<<rgrid, 128>>>(out, 0);

    caps_pass1<<<NCHK, 1024>>>();
    caps_reduce<<<rgrid, 128>>>(out, 1);

    caps_pass1<<<NCHK, 1024>>>();
    caps_reduce<<<rgrid, 128>>>(out, 2);
}

// round 7
// speedup vs baseline: 1.7480x; 1.7480x over previous
#include <cuda_runtime.h>
#include <cuda_fp16.h>

// CapsuleLayer dynamic routing — fp16-materialized u_hat, W-reuse GEMM,
// register-budgeted kernels (no spills).
// u [32,2048,16] f32, W [2048,16,1024] f32, out [32,1024] f32.

#define BB    32
#define NN    2048
#define KK    16
#define OUTC  1024

#define P0_NC 148     // pass0 n-chunks (x2 col-halves = 296 blocks)
#define P0_CH 14      // max n per pass0 chunk
#define P1_NC 37      // pass1 n-chunks (x8 b-groups = 296 blocks, 2/SM)

typedef unsigned long long ull;

// ---- scratch (device globals; runtime allocation is forbidden) ----
__device__ __half g_uhat_h[(size_t)BB * NN * OUTC];    // 134 MB
__device__ float  g_opart[(size_t)P0_NC * BB * OUTC];  // 19.4 MB
__device__ float  g_o[BB * OUTC];

__device__ __forceinline__ void ffma2(ull& d, ull a, ull b) {
    asm("fma.rn.f32x2 %0, %1, %2, %0;" : "+l"(d) : "l"(a), "l"(b));
}
__device__ __forceinline__ void fadd2(ull& d, ull a) {
    asm("add.rn.f32x2 %0, %0, %1;" : "+l"(d) : "l"(a));
}
__device__ __forceinline__ ull dup2(float x) {
    ull r; asm("mov.b64 %0, {%1, %1};" : "=l"(r) : "f"(x)); return r;
}
__device__ __forceinline__ float2 u2f(ull v) {
    float2 f; asm("mov.b64 {%0, %1}, %2;" : "=f"(f.x), "=f"(f.y) : "l"(v)); return f;
}

// ============ pass0: u_hat = u @ W (store fp16), + iteration-0 partials ======
// 512 threads: cv = tid&127 (vector col within this block's 512-col half),
// bg = tid>>7 (4 groups x 8 b each). ~100 regs/thread, cap 128 -> no spills.
__global__ __launch_bounds__(512, 1)
void caps_pass0(const float* __restrict__ u, const float* __restrict__ W)
{
    __shared__ float u_s[P0_CH][BB][KK];   // 28.7 KB

    const int cv  = threadIdx.x & 127;
    const int b0  = (threadIdx.x >> 7) * 8;
    const int n0  = (int)(((long long)blockIdx.y * NN) / P0_NC);
    const int n1  = (int)(((long long)(blockIdx.y + 1) * NN) / P0_NC);
    const int cnt = n1 - n0;
    const int colv = blockIdx.x * 128 + cv;   // global vector col (4 floats)

    for (int idx = threadIdx.x; idx < cnt * BB * KK; idx += 512) {
        int nn = idx >> 9, rem = idx & 511;
        int b = rem >> 4, k = rem & 15;
        u_s[nn][b][k] = u[((size_t)b * NN + (n0 + nn)) * KK + k];
    }
    __syncthreads();

    ull acc01[8], acc23[8];
    #pragma unroll
    for (int b = 0; b < 8; b++) { acc01[b] = 0ull; acc23[b] = 0ull; }

    const ulonglong2* Wv = reinterpret_cast<const ulonglong2*>(W) + colv;

    for (int nn = 0; nn < cnt; nn++) {
        const int n = n0 + nn;
        const ulonglong2* Wn = Wv + (size_t)n * KK * (OUTC / 4);

        ull t01[8], t23[8];
        #pragma unroll
        for (int b = 0; b < 8; b++) { t01[b] = 0ull; t23[b] = 0ull; }

        #pragma unroll
        for (int k4 = 0; k4 < KK / 4; k4++) {
            ulonglong2 wa = Wn[(size_t)(k4 * 4 + 0) * (OUTC / 4)];
            ulonglong2 wb = Wn[(size_t)(k4 * 4 + 1) * (OUTC / 4)];
            ulonglong2 wc = Wn[(size_t)(k4 * 4 + 2) * (OUTC / 4)];
            ulonglong2 wd = Wn[(size_t)(k4 * 4 + 3) * (OUTC / 4)];
            #pragma unroll
            for (int b = 0; b < 8; b++) {
                float4 uv = *reinterpret_cast<const float4*>(&u_s[nn][b0 + b][k4 * 4]);
                ffma2(t01[b], dup2(uv.x), wa.x); ffma2(t23[b], dup2(uv.x), wa.y);
                ffma2(t01[b], dup2(uv.y), wb.x); ffma2(t23[b], dup2(uv.y), wb.y);
                ffma2(t01[b], dup2(uv.z), wc.x); ffma2(t23[b], dup2(uv.z), wc.y);
                ffma2(t01[b], dup2(uv.w), wd.x); ffma2(t23[b], dup2(uv.w), wd.y);
            }
        }

        #pragma unroll
        for (int b = 0; b < 8; b++) {
            fadd2(acc01[b], t01[b]);
            fadd2(acc23[b], t23[b]);
            float2 f01 = u2f(t01[b]), f23 = u2f(t23[b]);
            __half2 h01 = __float22half2_rn(f01);
            __half2 h23 = __float22half2_rn(f23);
            uint2 st;
            st.x = *reinterpret_cast<unsigned*>(&h01);
            st.y = *reinterpret_cast<unsigned*>(&h23);
            *reinterpret_cast<uint2*>(
                &g_uhat_h[((size_t)(b0 + b) * NN + n) * OUTC + colv * 4]) = st;
        }
    }

    #pragma unroll
    for (int b = 0; b < 8; b++) {
        float2 f01 = u2f(acc01[b]), f23 = u2f(acc23[b]);
        *reinterpret_cast<float4*>(
            &g_opart[((size_t)blockIdx.y * BB + (b0 + b)) * OUTC + colv * 4]) =
            make_float4(f01.x, f01.y, f23.x, f23.y);
    }
}

// ====== pass1: fused logits + softmax(capsule axis) + o accumulation ========
// 512 threads = 4 b x 128 col-threads (uint4 = 8 fp16 cols each). ~45 regs.
__global__ __launch_bounds__(512, 2)
void caps_pass1()
{
    __shared__ float sm_b[4][BB];
    __shared__ float sm_c[4][BB];

    const int tid = threadIdx.x;
    const int bl  = tid >> 7;         // 0..3
    const int ct  = tid & 127;        // col-thread: halves [ct*8, ct*8+8)
    const int i   = ct >> 2;          // capsule (4 threads per capsule)
    const int b   = blockIdx.x * 4 + bl;

    const int n0  = (int)(((long long)blockIdx.y * NN) / P1_NC);
    const int n1  = (int)(((long long)(blockIdx.y + 1) * NN) / P1_NC);
    const int cnt = n1 - n0;

    float o_r[8];
    {
        const float4* op = reinterpret_cast<const float4*>(g_o + b * OUTC + ct * 8);
        float4 v0 = op[0], v1 = op[1];
        o_r[0] = v0.x; o_r[1] = v0.y; o_r[2] = v0.z; o_r[3] = v0.w;
        o_r[4] = v1.x; o_r[5] = v1.y; o_r[6] = v1.z; o_r[7] = v1.w;
    }

    float acc[8];
    #pragma unroll
    for (int j = 0; j < 8; j++) acc[j] = 0.f;

    const uint4* base = reinterpret_cast<const uint4*>(g_uhat_h)
                      + ((size_t)b * NN + n0) * (OUTC / 8) + ct;

    uint4 buf0 = base[0];
    uint4 buf1 = (cnt > 1) ? base[OUTC / 8] : buf0;

    for (int idx = 0; idx < cnt; idx++) {
        uint4 cur = buf0;
        buf0 = buf1;
        if (idx + 2 < cnt) buf1 = base[(size_t)(idx + 2) * (OUTC / 8)];

        // convert 8 halves -> 8 floats
        float f[8];
        {
            const unsigned* pw = reinterpret_cast<const unsigned*>(&cur);
            #pragma unroll
            for (int h = 0; h < 4; h++) {
                float2 fv = __half22float2(*reinterpret_cast<const __half2*>(&pw[h]));
                f[h * 2 + 0] = fv.x;
                f[h * 2 + 1] = fv.y;
            }
        }

        // logit partial over 8 cols, reduce over the 4 threads of capsule i
        float p = 0.f;
        #pragma unroll
        for (int j = 0; j < 8; j++) p = fmaf(f[j], o_r[j], p);
        p += __shfl_xor_sync(0xffffffffu, p, 1);
        p += __shfl_xor_sync(0xffffffffu, p, 2);
        if ((ct & 3) == 0) sm_b[bl][i] = p;
        __syncthreads();

        // softmax over capsules for the 4 b's (warps 0..3)
        if (tid < 128) {
            int bb = tid >> 5, ii = tid & 31;
            float v = sm_b[bb][ii];
            float m = v;
            #pragma unroll
            for (int off = 16; off > 0; off >>= 1)
                m = fmaxf(m, __shfl_xor_sync(0xffffffffu, m, off));
            float e = __expf(v - m);
            float s = e;
            #pragma unroll
            for (int off = 16; off > 0; off >>= 1)
                s += __shfl_xor_sync(0xffffffffu, s, off);
            sm_c[bb][ii] = e / s;
        }
        __syncthreads();

        float ci = sm_c[bl][i];
        #pragma unroll
        for (int j = 0; j < 8; j++) acc[j] = fmaf(ci, f[j], acc[j]);
    }

    float* dst = g_opart + ((size_t)blockIdx.y * BB + b) * OUTC + ct * 8;
    *reinterpret_cast<float4*>(dst)     = make_float4(acc[0], acc[1], acc[2], acc[3]);
    *reinterpret_cast<float4*>(dst + 4) = make_float4(acc[4], acc[5], acc[6], acc[7]);
}

// ============ reduce: sum chunks, l2-normalize (->g_o) or squash (->out) =====
__global__ __launch_bounds__(128)
void caps_reduce(float* __restrict__ out, int nch, int mode)
{
    const int b   = blockIdx.x;
    const int col = blockIdx.y * 128 + threadIdx.x;

    const float* p = g_opart + (size_t)b * OUTC + col;
    const size_t S = (size_t)BB * OUTC;

    float a0 = 0.f, a1 = 0.f, a2 = 0.f, a3 = 0.f;
    float a4 = 0.f, a5 = 0.f, a6 = 0.f, a7 = 0.f;
    int ch = 0;
    #pragma unroll 1
    for (; ch + 8 <= nch; ch += 8) {
        a0 += p[(ch + 0) * S]; a1 += p[(ch + 1) * S];
        a2 += p[(ch + 2) * S]; a3 += p[(ch + 3) * S];
        a4 += p[(ch + 4) * S]; a5 += p[(ch + 5) * S];
        a6 += p[(ch + 6) * S]; a7 += p[(ch + 7) * S];
    }
    for (; ch < nch; ch++) a0 += p[ch * S];
    float s = ((a0 + a1) + (a2 + a3)) + ((a4 + a5) + (a6 + a7));

    if (mode == 0) s *= (1.0f / 32.0f);

    float q = s * s;
    #pragma unroll
    for (int off = 16; off > 0; off >>= 1)
        q += __shfl_xor_sync(0xffffffffu, q, off);

    if (mode < 2) {
        g_o[b * OUTC + col] = s * rsqrtf(fmaxf(q, 1e-12f));            // l2_normalize
    } else {
        out[(size_t)b * OUTC + col] = (q / (1.f + q)) * s * rsqrtf(q + 1e-7f);  // squash
    }
}

extern "C" void kernel_launch(void* const* d_in, const int* in_sizes, int n_in,
                              void* d_out, int out_size)
{
    const float* u = (const float*)d_in[0];
    const float* W = (const float*)d_in[1];
    if (n_in >= 2 && in_sizes[0] > in_sizes[1]) {  // defensive: u is the smaller input
        const float* t = u; u = W; W = t;
    }
    float* out = (float*)d_out;

    dim3 rgrid(BB, 8);

    caps_pass0<<<dim3(2, P0_NC), 512>>>(u, W);
    caps_reduce<<<rgrid, 128>>>(out, P0_NC, 0);

    caps_pass1<<<dim3(BB / 4, P1_NC), 512>>>();
    caps_reduce<<<rgrid, 128>>>(out, P1_NC, 1);

    caps_pass1<<<dim3(BB / 4, P1_NC), 512>>>();
    caps_reduce<<<rgrid, 128>>>(out, P1_NC, 2);
}